// round 2
// baseline (speedup 1.0000x reference)
#include <cuda_runtime.h>

#define OH 121          // output patches per dim: 128 - 8 + 1
#define NIMG 8

// ---------------- device scratch (no allocations allowed) ----------------
__device__ float g_S[256 * 256];                    // LISTA mutual-inhibition matrix (tf32-rounded)
__device__ float g_XP[NIMG * 128 * 128 * 64];       // x_pred per (img, pr, pc, d) ~33.5MB

// ---------------- packed fp32x2 helpers (full-rate FMA on Blackwell) -----
static __device__ __forceinline__ unsigned long long pk2(float lo, float hi) {
    unsigned long long r;
    unsigned int l = __float_as_uint(lo), h = __float_as_uint(hi);
    asm("mov.b64 %0, {%1,%2};" : "=l"(r) : "r"(l), "r"(h));
    return r;
}
static __device__ __forceinline__ void upk2(unsigned long long v, float& lo, float& hi) {
    unsigned int l, h;
    asm("mov.b64 {%0,%1}, %2;" : "=r"(l), "=r"(h) : "l"(v));
    lo = __uint_as_float(l); hi = __uint_as_float(h);
}
static __device__ __forceinline__ void fma2(unsigned long long& d,
                                            unsigned long long a, unsigned long long b) {
    asm("fma.rn.f32x2 %0, %1, %2, %0;" : "+l"(d) : "l"(a), "l"(b));
}

// TF32 rounding (emulate XLA/cuBLAS tf32 matmul operand rounding)
static __device__ __forceinline__ float tf32r(float v) {
    unsigned int r;
    asm("cvt.rna.tf32.f32 %0, %1;" : "=r"(r) : "f"(v));
    return __uint_as_float(r);
}

static __device__ __forceinline__ float softthr(float v, float t) {
    float r = fmaxf(fabsf(v) - t, 0.0f);
    float s = (v > 0.0f) ? 1.0f : ((v < 0.0f) ? -1.0f : 0.0f);   // exact sign(0)=0
    return s * r;
}

// ---------------- kernel 1: S = tf32( I - (D^T D)/c ), D^T D in tf32 -----
__global__ void sprep_kernel(const float* __restrict__ Dict, const float* __restrict__ cp) {
    int k = blockIdx.x, n = threadIdx.x;
    float c = cp[0];
    float s = 0.0f;
#pragma unroll 8
    for (int r = 0; r < 64; r++)
        s = fmaf(tf32r(Dict[r * 256 + k]), tf32r(Dict[r * 256 + n]), s);
    g_S[k * 256 + n] = tf32r((k == n ? 1.0f : 0.0f) - s / c);
}

// ---------------- kernel 2: per-tile LISTA pipeline ----------------------
// CTA: 8x8 patch block of one image (64 patches), 256 threads.
// smem: U 16KB | scr 32KB (h1/h3/S-chunk) | yc 64KB (h2/y/c/DictT) | z 64KB | thr
__global__ __launch_bounds__(256, 1) void lista_kernel(
    const float* __restrict__ x, const float* __restrict__ Dict,
    const float* __restrict__ cp, const float* __restrict__ wp,
    const float* __restrict__ W1, const float* __restrict__ b1,
    const float* __restrict__ W2, const float* __restrict__ b2,
    const float* __restrict__ W3, const float* __restrict__ b3,
    const float* __restrict__ W4, const float* __restrict__ b4)
{
    extern __shared__ float sm[];
    float* U   = sm;              // 64*64   = 4096
    float* scr = sm + 4096;       // 64*128  = 8192
    float* yc  = sm + 12288;      // 64*256  = 16384
    float* z   = sm + 28672;      // 64*256  = 16384
    float* thr = sm + 45056;      // 64

    const int tid = threadIdx.x;
    const int img = blockIdx.z;
    const int pr0 = blockIdx.y * 8, pc0 = blockIdx.x * 8;
    const float c = cp[0], cinv = 1.0f / c, wv = wp[0];
    const float* xi = x + img * 16384;

    // ---- build U (zero-fill invalid patches), tf32-rounded (matmul operand only)
    for (int idx = tid; idx < 4096; idx += 256) {
        int m = idx >> 6, d = idx & 63;
        int pr = pr0 + (m >> 3), pc = pc0 + (m & 7);
        float v = 0.0f;
        if (pr < OH && pc < OH) v = xi[(pr + (d >> 3)) * 128 + pc + (d & 7)];
        U[idx] = tf32r(v);
    }
    __syncthreads();

    // ---- MLP stage A: h1[64][128] = relu(U@W1+b1) -> scr (tf32-rounded) ----
    {
        int j = tid & 127;
        int mbase = tid >> 7;   // 0..1, m = mbase + 2t
        float acc[32];
#pragma unroll
        for (int t = 0; t < 32; t++) acc[t] = 0.0f;
        for (int r0 = 0; r0 < 64; r0 += 16) {
            float wc[16];
#pragma unroll
            for (int rr = 0; rr < 16; rr++) wc[rr] = tf32r(W1[(r0 + rr) * 128 + j]);
#pragma unroll
            for (int t = 0; t < 32; t++) {
                const float4* up = (const float4*)(U + (mbase + 2 * t) * 64 + r0);
#pragma unroll
                for (int q4 = 0; q4 < 4; q4++) {
                    float4 u = up[q4];
                    acc[t] = fmaf(u.x, wc[q4 * 4 + 0], acc[t]);
                    acc[t] = fmaf(u.y, wc[q4 * 4 + 1], acc[t]);
                    acc[t] = fmaf(u.z, wc[q4 * 4 + 2], acc[t]);
                    acc[t] = fmaf(u.w, wc[q4 * 4 + 3], acc[t]);
                }
            }
        }
        float bb = b1[j];
#pragma unroll
        for (int t = 0; t < 32; t++)
            scr[(mbase + 2 * t) * 128 + j] = tf32r(fmaxf(acc[t] + bb, 0.0f));
    }
    __syncthreads();

    // ---- MLP stage B: h2[64][64] = relu(h1@W2+b2) -> yc[0:4096) (tf32) ----
    {
        int j = tid & 63;
        int mbase = tid >> 6;   // 0..3, m = mbase + 4t
        float acc[16];
#pragma unroll
        for (int t = 0; t < 16; t++) acc[t] = 0.0f;
        for (int r0 = 0; r0 < 128; r0 += 16) {
            float wc[16];
#pragma unroll
            for (int rr = 0; rr < 16; rr++) wc[rr] = tf32r(W2[(r0 + rr) * 64 + j]);
#pragma unroll
            for (int t = 0; t < 16; t++) {
                const float4* hp = (const float4*)(scr + (mbase + 4 * t) * 128 + r0);
#pragma unroll
                for (int q4 = 0; q4 < 4; q4++) {
                    float4 u = hp[q4];
                    acc[t] = fmaf(u.x, wc[q4 * 4 + 0], acc[t]);
                    acc[t] = fmaf(u.y, wc[q4 * 4 + 1], acc[t]);
                    acc[t] = fmaf(u.z, wc[q4 * 4 + 2], acc[t]);
                    acc[t] = fmaf(u.w, wc[q4 * 4 + 3], acc[t]);
                }
            }
        }
        float bb = b2[j];
#pragma unroll
        for (int t = 0; t < 16; t++)
            yc[(mbase + 4 * t) * 64 + j] = tf32r(fmaxf(acc[t] + bb, 0.0f));
    }
    __syncthreads();

    // ---- MLP stage C: h3[64][32] = relu(h2@W3+b3) -> scr[0:2048) (tf32) ----
    {
        int j = tid & 31;
        int mbase = tid >> 5;   // 0..7, m = mbase + 8t
        float acc[8];
#pragma unroll
        for (int t = 0; t < 8; t++) acc[t] = 0.0f;
        for (int r0 = 0; r0 < 64; r0 += 16) {
            float wc[16];
#pragma unroll
            for (int rr = 0; rr < 16; rr++) wc[rr] = tf32r(W3[(r0 + rr) * 32 + j]);
#pragma unroll
            for (int t = 0; t < 8; t++) {
                const float4* hp = (const float4*)(yc + (mbase + 8 * t) * 64 + r0);
#pragma unroll
                for (int q4 = 0; q4 < 4; q4++) {
                    float4 u = hp[q4];
                    acc[t] = fmaf(u.x, wc[q4 * 4 + 0], acc[t]);
                    acc[t] = fmaf(u.y, wc[q4 * 4 + 1], acc[t]);
                    acc[t] = fmaf(u.z, wc[q4 * 4 + 2], acc[t]);
                    acc[t] = fmaf(u.w, wc[q4 * 4 + 3], acc[t]);
                }
            }
        }
        float bb = b3[j];
#pragma unroll
        for (int t = 0; t < 8; t++)
            scr[(mbase + 8 * t) * 32 + j] = tf32r(fmaxf(acc[t] + bb, 0.0f));
    }
    __syncthreads();

    // ---- MLP stage D: thr = (h3@W4+b4)/c ----
    if (tid < 64) {
        const float* hm = scr + tid * 32;
        float a = b4[0];
#pragma unroll
        for (int r = 0; r < 32; r++) a = fmaf(hm[r], tf32r(W4[r]), a);
        thr[tid] = a / c;   // IEEE divide, matches reference lam/c
    }
    __syncthreads();

    // ---- y = U@Dict ; yc = y/c ; z0 = tf32(soft(y, thr)) ----
    {
        int n = tid;  // one atom column per thread
        for (int m0 = 0; m0 < 64; m0 += 8) {
            float acc[8];
#pragma unroll
            for (int i = 0; i < 8; i++) acc[i] = 0.0f;
#pragma unroll 4
            for (int r0 = 0; r0 < 64; r0 += 4) {
                float dv0 = tf32r(Dict[(r0 + 0) * 256 + n]);
                float dv1 = tf32r(Dict[(r0 + 1) * 256 + n]);
                float dv2 = tf32r(Dict[(r0 + 2) * 256 + n]);
                float dv3 = tf32r(Dict[(r0 + 3) * 256 + n]);
#pragma unroll
                for (int i = 0; i < 8; i++) {
                    float4 u = *(const float4*)(U + (m0 + i) * 64 + r0);
                    acc[i] = fmaf(u.x, dv0, acc[i]);
                    acc[i] = fmaf(u.y, dv1, acc[i]);
                    acc[i] = fmaf(u.z, dv2, acc[i]);
                    acc[i] = fmaf(u.w, dv3, acc[i]);
                }
            }
#pragma unroll
            for (int i = 0; i < 8; i++) {
                int m = m0 + i;
                float yv = acc[i];
                z[m * 256 + n]  = tf32r(softthr(yv, thr[m]));
                yc[m * 256 + n] = yv * cinv;   // additive term, stays fp32
            }
        }
    }
    __syncthreads();   // yc/z fully written before cross-thread reads (race fix)

    // ---- LISTA main loop: z = soft(z@S + y/c, thr), x7 -----------------
    // z and S are tf32-rounded at their store points -> tf32-emulated matmul,
    // fp32 accumulate. Zero extra ops in this hot loop.
    const int tx = tid & 15, ty = tid >> 4;
    for (int it = 0; it < 7; it++) {
        unsigned long long acc[4][8];
#pragma unroll
        for (int i = 0; i < 4; i++) {
            const float4* yr = (const float4*)(yc + (ty * 4 + i) * 256 + tx * 16);
#pragma unroll
            for (int jj = 0; jj < 4; jj++) {
                float4 v = yr[jj];
                acc[i][2 * jj]     = pk2(v.x, v.y);
                acc[i][2 * jj + 1] = pk2(v.z, v.w);
            }
        }
        for (int k0 = 0; k0 < 256; k0 += 32) {
            __syncthreads();   // previous chunk readers / z writers done
            {
                const float4* src = (const float4*)(g_S + k0 * 256);
                float4* dst = (float4*)scr;
#pragma unroll
                for (int t2 = 0; t2 < 8; t2++) dst[tid + t2 * 256] = src[tid + t2 * 256];
            }
            __syncthreads();
#pragma unroll 2
            for (int k = 0; k < 32; k++) {
                unsigned long long sv[8];
                const float4* srow = (const float4*)(scr + k * 256 + tx * 16);
#pragma unroll
                for (int jj = 0; jj < 4; jj++) {
                    float4 v = srow[jj];
                    sv[2 * jj]     = pk2(v.x, v.y);
                    sv[2 * jj + 1] = pk2(v.z, v.w);
                }
#pragma unroll
                for (int i = 0; i < 4; i++) {
                    float zr = z[(ty * 4 + i) * 256 + k0 + k];
                    unsigned long long zz = pk2(zr, zr);
#pragma unroll
                    for (int j = 0; j < 8; j++) fma2(acc[i][j], zz, sv[j]);
                }
            }
        }
        __syncthreads();   // all reads of z complete before overwrite
#pragma unroll
        for (int i = 0; i < 4; i++) {
            int m = ty * 4 + i;
            float t = thr[m];
            float* zr = z + m * 256 + tx * 16;
#pragma unroll
            for (int j = 0; j < 8; j++) {
                float lo, hi;
                upk2(acc[i][j], lo, hi);
                zr[2 * j]     = tf32r(softthr(lo, t));
                zr[2 * j + 1] = tf32r(softthr(hi, t));
            }
        }
    }
    __syncthreads();

    // ---- stage Dict^T into yc: DT[k][d] = tf32(Dict[d][k]) ----
    for (int idx = tid; idx < 16384; idx += 256) {
        int d = idx >> 8, k = idx & 255;
        yc[k * 64 + d] = tf32r(Dict[idx]);
    }
    __syncthreads();

    // ---- x_pred = clip(z @ Dict^T, 0, 1) * w -> g_XP ----
    {
        // thread tile: 4 rows (ty) x 4 d-cols (tx*4), f32x2 pairs
        unsigned long long acc[4][2];
#pragma unroll
        for (int i = 0; i < 4; i++) { acc[i][0] = 0ull; acc[i][1] = 0ull; }
#pragma unroll 4
        for (int k = 0; k < 256; k++) {
            float4 v = *(const float4*)(yc + k * 64 + tx * 4);
            unsigned long long d01 = pk2(v.x, v.y), d23 = pk2(v.z, v.w);
#pragma unroll
            for (int i = 0; i < 4; i++) {
                float zr = z[(ty * 4 + i) * 256 + k];
                unsigned long long zz = pk2(zr, zr);
                fma2(acc[i][0], zz, d01);
                fma2(acc[i][1], zz, d23);
            }
        }
#pragma unroll
        for (int i = 0; i < 4; i++) {
            int m = ty * 4 + i;
            int pr = pr0 + (m >> 3), pc = pc0 + (m & 7);
            if (pr >= OH || pc >= OH) continue;
            float v0, v1, v2, v3;
            upk2(acc[i][0], v0, v1);
            upk2(acc[i][1], v2, v3);
            float4 o;
            o.x = fminf(fmaxf(v0, 0.0f), 1.0f) * wv;
            o.y = fminf(fmaxf(v1, 0.0f), 1.0f) * wv;
            o.z = fminf(fmaxf(v2, 0.0f), 1.0f) * wv;
            o.w = fminf(fmaxf(v3, 0.0f), 1.0f) * wv;
            int gp = img * 16384 + pr * 128 + pc;
            *(float4*)(g_XP + (size_t)gp * 64 + tx * 4) = o;
        }
    }
}

// ---------------- kernel 3: gather fold + analytic denominator -----------
__global__ void finalize_kernel(float* __restrict__ out, const float* __restrict__ wp) {
    int idx = blockIdx.x * 256 + threadIdx.x;           // 131072 pixels
    int img = idx >> 14, i = (idx >> 7) & 127, j = idx & 127;
    float s = 0.0f;
#pragma unroll
    for (int di = 0; di < 8; di++) {
        int pr = i - di;
        if (pr < 0 || pr >= OH) continue;
#pragma unroll
        for (int dj = 0; dj < 8; dj++) {
            int pc = j - dj;
            if (pc < 0 || pc >= OH) continue;
            s += g_XP[(size_t)(img * 16384 + pr * 128 + pc) * 64 + di * 8 + dj];
        }
    }
    int ci = min(min(i + 1, 8), 128 - i);
    int cj = min(min(j + 1, 8), 128 - j);
    out[idx] = s / (wp[0] * (float)(ci * cj));
}

// ---------------- launch ----------------
extern "C" void kernel_launch(void* const* d_in, const int* in_sizes, int n_in,
                              void* d_out, int out_size) {
    const float* x    = (const float*)d_in[0];
    const float* Dict = (const float*)d_in[1];
    const float* c    = (const float*)d_in[2];
    const float* w    = (const float*)d_in[3];
    const float* W1   = (const float*)d_in[4];
    const float* b1   = (const float*)d_in[5];
    const float* W2   = (const float*)d_in[6];
    const float* b2   = (const float*)d_in[7];
    const float* W3   = (const float*)d_in[8];
    const float* b3   = (const float*)d_in[9];
    const float* W4   = (const float*)d_in[10];
    const float* b4   = (const float*)d_in[11];
    float* out = (float*)d_out;

    const int SMEM_BYTES = 45120 * 4;   // 176.25 KB dynamic smem
    cudaFuncSetAttribute(lista_kernel, cudaFuncAttributeMaxDynamicSharedMemorySize, SMEM_BYTES);

    sprep_kernel<<<256, 256>>>(Dict, c);
    lista_kernel<<<dim3(16, 16, NIMG), 256, SMEM_BYTES>>>(
        x, Dict, c, w, W1, b1, W2, b2, W3, b3, W4, b4);
    finalize_kernel<<<512, 256>>>(out, w);
}